// round 7
// baseline (speedup 1.0000x reference)
#include <cuda_runtime.h>
#include <cuda_bf16.h>
#include <cstdint>

#define N_NODES 100000
#define N_EDGES 1600000
#define N_GRAPHS 256
#define D 128
#define L 3
#define PROJ 128
#define NUM_CLASSES 10

// ---------------- device scratch ----------------
__device__ float g_ha[N_NODES * D];   // feature ping-pong buffer A
__device__ float g_hb[N_NODES * D];   // feature ping-pong buffer B
__device__ int   g_counts[N_NODES];
__device__ int   g_offs[N_NODES];
__device__ int   g_cursor[N_NODES];
__device__ int   g_bsum[128];
__device__ int   g_eidx[N_EDGES];
__device__ int   g_cg[N_GRAPHS];
__device__ float g_pooled[L * N_GRAPHS * D];
// packed mma-fragment weights: [l][mat(4)][2048] uint4; mat: 0=w1hi 1=w1lo 2=w2hi 3=w2lo
__device__ __align__(16) uint4 g_wpack[L * 4 * 2048];
__device__ float g_b1e[L * D];
__device__ int   g_is64;

// ping-pong selection: layer l reads bufs_in[l], writes bufs_out[l]
// l=0: x -> A ; l=1: A -> B ; l=2: B -> A
__device__ __forceinline__ const float* layer_in(int l, const float* x) {
    if (l == 0) return x;
    return (l == 1) ? g_ha : g_hb;
}
__device__ __forceinline__ float* layer_out(int l) {
    return (l == 1) ? g_hb : g_ha;
}

// ---------------- dtype detection: int64 vs int32 indices ----------------
__global__ void detect_kernel(const int* __restrict__ ei_words) {
    int all0 = 1;
    for (int i = 1; i < 128; i += 2)
        if (ei_words[i] != 0) { all0 = 0; break; }
    g_is64 = all0;
}

__device__ __forceinline__ int idx_at(const void* p, long long i) {
    if (g_is64) return (int)__ldg(&((const long long*)p)[i]);
    return __ldg(&((const int*)p)[i]);
}

// ---------------- setup kernels ----------------
__global__ void zero_kernel() {
    int i = blockIdx.x * blockDim.x + threadIdx.x;
    if (i < N_NODES) g_counts[i] = 0;
    if (i < N_GRAPHS) g_cg[i] = 0;
    if (i < L * N_GRAPHS * D) g_pooled[i] = 0.f;
}

__global__ void hist_edges(const void* __restrict__ ei) {
    int e = blockIdx.x * blockDim.x + threadIdx.x;
    if (e < N_EDGES) {
        int d = idx_at(ei, (long long)N_EDGES + e);
        atomicAdd(&g_counts[d], 1);
    }
}

// smem histogram: batch is sorted so each block touches few graphs
__global__ void hist_batch(const void* __restrict__ batch) {
    __shared__ int sh[N_GRAPHS];
    int tid = threadIdx.x;
    if (tid < N_GRAPHS) sh[tid] = 0;
    __syncthreads();
    int i = blockIdx.x * 1024 + tid;
    if (i < N_NODES) atomicAdd(&sh[idx_at(batch, i)], 1);
    __syncthreads();
    if (tid < N_GRAPHS && sh[tid]) atomicAdd(&g_cg[tid], sh[tid]);
}

__global__ void scan1() {
    __shared__ int s[1024];
    int i = blockIdx.x * 1024 + threadIdx.x;
    int v = (i < N_NODES) ? g_counts[i] : 0;
    s[threadIdx.x] = v;
    __syncthreads();
    for (int d = 1; d < 1024; d <<= 1) {
        int t = 0;
        if ((int)threadIdx.x >= d) t = s[threadIdx.x - d];
        __syncthreads();
        s[threadIdx.x] += t;
        __syncthreads();
    }
    if (i < N_NODES) g_offs[i] = s[threadIdx.x] - v;  // exclusive
    if (threadIdx.x == 1023) g_bsum[blockIdx.x] = s[1023];
}

__global__ void scan2() {
    int acc = 0;
    for (int b = 0; b < 98; b++) { int v = g_bsum[b]; g_bsum[b] = acc; acc += v; }
}

__global__ void scan3() {
    int i = blockIdx.x * blockDim.x + threadIdx.x;
    if (i < N_NODES) {
        int off = g_offs[i] + g_bsum[i >> 10];
        g_offs[i] = off;
        g_cursor[i] = off;
    }
}

__global__ void scatter_edges(const void* __restrict__ ei) {
    int e = blockIdx.x * blockDim.x + threadIdx.x;
    if (e < N_EDGES) {
        int d = idx_at(ei, (long long)N_EDGES + e);
        int s = idx_at(ei, e);
        int p = atomicAdd(&g_cursor[d], 1);
        g_eidx[p] = s;
    }
}

// ---------------- weight conversion: fold BN, split hi/lo, pack to fragment order ----------------
// Fragment layout per matrix (2048 uint4): index = (kk*8 + nbp)*32 + lane.
// uint4 = { (n0,kb),(n0,kb+1) | (n0,kb+8),(n0,kb+9) | (n1,kb..) | (n1,kb+8..) }
// with g=lane>>2, t4=lane&3, kb=kk*16+t4*2, n0=(2*nbp)*8+g, n1=n0+8.
__device__ __forceinline__ uint32_t pack2(float a, float b, int lo) {
    __nv_bfloat16 ha = __float2bfloat16(a), hb = __float2bfloat16(b);
    if (lo) {
        ha = __float2bfloat16(a - __bfloat162float(__float2bfloat16(a)));
        hb = __float2bfloat16(b - __bfloat162float(__float2bfloat16(b)));
    }
    return (uint32_t)(*(unsigned short*)&ha) | ((uint32_t)(*(unsigned short*)&hb) << 16);
}

__global__ void convert_weights(const float* __restrict__ W1, const float* __restrict__ W2,
                                const float* __restrict__ b1,
                                const float* __restrict__ bng, const float* __restrict__ bnb,
                                const float* __restrict__ bnm, const float* __restrict__ bnv) {
    int t = blockIdx.x * blockDim.x + threadIdx.x;
    if (t < L * D) {
        float scale = bng[t] * rsqrtf(bnv[t] + 1e-5f);
        g_b1e[t] = (b1[t] - bnm[t]) * scale + bnb[t];
    }
    if (t >= L * 4 * 2048) return;
    int l = t / (4 * 2048);
    int r = t % (4 * 2048);
    int mat = r / 2048;          // 0=w1hi 1=w1lo 2=w2hi 3=w2lo
    int fg = (r % 2048) / 32;    // kk*8+nbp
    int lane = r % 32;
    int kk = fg >> 3, nbp = fg & 7;
    int g = lane >> 2, t4 = lane & 3;
    int kb = kk * 16 + t4 * 2;
    int n0 = (2 * nbp) * 8 + g;
    int n1 = n0 + 8;
    const float* W = (mat < 2) ? W1 : W2;
    int lo = mat & 1;
    // W[l][k][n]; fold BN scale into W1 (per output column n)
    float s0 = 1.f, s1 = 1.f;
    if (mat < 2) {
        s0 = bng[l * D + n0] * rsqrtf(bnv[l * D + n0] + 1e-5f);
        s1 = bng[l * D + n1] * rsqrtf(bnv[l * D + n1] + 1e-5f);
    }
    const float* Wl = W + l * D * D;
    uint4 v;
    v.x = pack2(Wl[kb * D + n0] * s0, Wl[(kb + 1) * D + n0] * s0, lo);
    v.y = pack2(Wl[(kb + 8) * D + n0] * s0, Wl[(kb + 9) * D + n0] * s0, lo);
    v.z = pack2(Wl[kb * D + n1] * s1, Wl[(kb + 1) * D + n1] * s1, lo);
    v.w = pack2(Wl[(kb + 8) * D + n1] * s1, Wl[(kb + 9) * D + n1] * s1, lo);
    g_wpack[t] = v;
}

// ---------------- fused aggregate + MLP ----------------
__device__ __forceinline__ void mma_bf16(float* c,
                                         uint32_t a0, uint32_t a1, uint32_t a2, uint32_t a3,
                                         uint32_t b0, uint32_t b1) {
    asm volatile(
        "mma.sync.aligned.m16n8k16.row.col.f32.bf16.bf16.f32 "
        "{%0,%1,%2,%3}, {%4,%5,%6,%7}, {%8,%9}, {%0,%1,%2,%3};"
        : "+f"(c[0]), "+f"(c[1]), "+f"(c[2]), "+f"(c[3])
        : "r"(a0), "r"(a1), "r"(a2), "r"(a3), "r"(b0), "r"(b1));
}

#define SM_PITCH 136

__device__ __forceinline__ void gemm_pass(const __nv_bfloat16* sA, const uint4* __restrict__ wp,
                                          int r0, int lane, int t4, float acc[16][4]) {
#pragma unroll
    for (int kk = 0; kk < 8; kk++) {
        int kb = kk * 16 + t4 * 2;
        uint32_t a0 = *(const uint32_t*)(sA + r0 * SM_PITCH + kb);
        uint32_t a1 = *(const uint32_t*)(sA + (r0 + 8) * SM_PITCH + kb);
        uint32_t a2 = *(const uint32_t*)(sA + r0 * SM_PITCH + kb + 8);
        uint32_t a3 = *(const uint32_t*)(sA + (r0 + 8) * SM_PITCH + kb + 8);
        const uint4* base = wp + kk * 8 * 32 + lane;
#pragma unroll
        for (int nbp = 0; nbp < 8; nbp++) {
            uint4 b = __ldg(base + nbp * 32);
            mma_bf16(acc[2 * nbp], a0, a1, a2, a3, b.x, b.y);
            mma_bf16(acc[2 * nbp + 1], a0, a1, a2, a3, b.z, b.w);
        }
    }
}

__device__ __forceinline__ void store_split(__nv_bfloat16* sHi, __nv_bfloat16* sLo,
                                            int r, int c, float x, float y) {
    __nv_bfloat16 hx = __float2bfloat16(x), hy = __float2bfloat16(y);
    unsigned int uh = (unsigned)(*(unsigned short*)&hx) | ((unsigned)(*(unsigned short*)&hy) << 16);
    __nv_bfloat16 lx = __float2bfloat16(x - __bfloat162float(hx));
    __nv_bfloat16 ly = __float2bfloat16(y - __bfloat162float(hy));
    unsigned int ul = (unsigned)(*(unsigned short*)&lx) | ((unsigned)(*(unsigned short*)&ly) << 16);
    *(unsigned int*)(sHi + r * SM_PITCH + c) = uh;
    *(unsigned int*)(sLo + r * SM_PITCH + c) = ul;
}

#define SMEM_MLP (2 * 128 * SM_PITCH * 2)

__global__ void __launch_bounds__(256) mlp_kernel(int l, const float* __restrict__ x,
                                                  const float* __restrict__ b2all) {
    extern __shared__ __nv_bfloat16 sm[];
    __nv_bfloat16* sHi = sm;
    __nv_bfloat16* sLo = sm + 128 * SM_PITCH;
    const int tid = threadIdx.x;
    const int tile = blockIdx.x * 128;
    const int wid = tid >> 5, lane = tid & 31;

    const float* hin = layer_in(l, x);
    float* hout = layer_out(l);

    // ---- phase A: gather-aggregate directly into smem hi/lo tiles ----
    // reads hin (prev layer), writes hout (this layer) -> no cross-block race
    const float4* h4 = (const float4*)hin;
    for (int i = 0; i < 16; i++) {
        int r = wid * 16 + i;
        int node = tile + r;
        float4 acc4;
        if (node < N_NODES) {
            acc4 = h4[node * 32 + lane];
            int s = g_offs[node];
            int e = s + g_counts[node];
            for (int j = s; j < e; j++) {
                int src = g_eidx[j];
                float4 v = __ldg(&h4[src * 32 + lane]);
                acc4.x += v.x; acc4.y += v.y; acc4.z += v.z; acc4.w += v.w;
            }
        } else {
            acc4 = make_float4(0.f, 0.f, 0.f, 0.f);
        }
        int c = lane * 4;
        store_split(sHi, sLo, r, c, acc4.x, acc4.y);
        store_split(sHi, sLo, r, c + 2, acc4.z, acc4.w);
    }
    __syncthreads();

    const int g = lane >> 2, t4 = lane & 3;
    const int r0 = wid * 16 + g;

    const uint4* wl = g_wpack + l * 4 * 2048;
    const float* b1e = g_b1e + l * D;
    const float* b2 = b2all + l * D;

    float acc[16][4];
#pragma unroll
    for (int nb = 0; nb < 16; nb++)
#pragma unroll
        for (int j = 0; j < 4; j++) acc[nb][j] = 0.f;

    // GEMM1: 3-term compensated bf16 (BN folded into w1/b1e)
    gemm_pass(sHi, wl + 0 * 2048, r0, lane, t4, acc);  // hi*hi
    gemm_pass(sHi, wl + 1 * 2048, r0, lane, t4, acc);  // hi*lo
    gemm_pass(sLo, wl + 0 * 2048, r0, lane, t4, acc);  // lo*hi
    __syncthreads();

    // epilogue1: +b1e, relu, resplit to smem
#pragma unroll
    for (int nb = 0; nb < 16; nb++) {
        int c0 = nb * 8 + t4 * 2;
        float bb0 = b1e[c0], bb1 = b1e[c0 + 1];
        float v00 = fmaxf(acc[nb][0] + bb0, 0.f);
        float v01 = fmaxf(acc[nb][1] + bb1, 0.f);
        float v10 = fmaxf(acc[nb][2] + bb0, 0.f);
        float v11 = fmaxf(acc[nb][3] + bb1, 0.f);
        store_split(sHi, sLo, r0, c0, v00, v01);
        store_split(sHi, sLo, r0 + 8, c0, v10, v11);
    }
    __syncthreads();

#pragma unroll
    for (int nb = 0; nb < 16; nb++)
#pragma unroll
        for (int j = 0; j < 4; j++) acc[nb][j] = 0.f;

    // GEMM2
    gemm_pass(sHi, wl + 2 * 2048, r0, lane, t4, acc);
    gemm_pass(sHi, wl + 3 * 2048, r0, lane, t4, acc);
    gemm_pass(sLo, wl + 2 * 2048, r0, lane, t4, acc);

    // epilogue2: +b2, relu, store hout
    int row0 = tile + r0;
    int row1 = tile + r0 + 8;
#pragma unroll
    for (int nb = 0; nb < 16; nb++) {
        int c0 = nb * 8 + t4 * 2;
        float bb0 = b2[c0], bb1 = b2[c0 + 1];
        float v00 = fmaxf(acc[nb][0] + bb0, 0.f);
        float v01 = fmaxf(acc[nb][1] + bb1, 0.f);
        float v10 = fmaxf(acc[nb][2] + bb0, 0.f);
        float v11 = fmaxf(acc[nb][3] + bb1, 0.f);
        if (row0 < N_NODES) *(float2*)&hout[row0 * 128 + c0] = make_float2(v00, v01);
        if (row1 < N_NODES) *(float2*)&hout[row1 * 128 + c0] = make_float2(v10, v11);
    }
}

// ---------------- pooling: segment-sum of layer-l output into pooled[l] ----------------
#define POOL_NODES 512
__global__ void pool_kernel(const void* __restrict__ batch, int l) {
    const float* h = layer_out(l);
    int t = threadIdx.x;  // 0..127 feature index
    int start = blockIdx.x * POOL_NODES;
    if (start >= N_NODES) return;
    int end = min(start + POOL_NODES, N_NODES);
    int cur = idx_at(batch, start);
    float acc = 0.f;
    for (int n = start; n < end; n++) {
        int gid = idx_at(batch, n);
        if (gid != cur) {
            atomicAdd(&g_pooled[(l * N_GRAPHS + cur) * D + t], acc);
            acc = 0.f;
            cur = gid;
        }
        acc += h[n * D + t];
    }
    atomicAdd(&g_pooled[(l * N_GRAPHS + cur) * D + t], acc);
}

// ---------------- head ----------------
__global__ void head_kernel(const float* __restrict__ Wp, const float* __restrict__ bp,
                            const float* __restrict__ Wc, const float* __restrict__ bc,
                            float* __restrict__ out) {
    __shared__ float zs[PROJ];
    int gph = blockIdx.x, t = threadIdx.x;
    float inv = 1.f / fmaxf((float)g_cg[gph], 1.f);
    float acc = bp[t];
#pragma unroll
    for (int l = 0; l < L; l++) {
        const float* pl = &g_pooled[(l * N_GRAPHS + gph) * D];
#pragma unroll 4
        for (int k = 0; k < D; k++) acc += pl[k] * inv * Wp[(l * D + k) * PROJ + t];
    }
    zs[t] = acc;
    out[gph * PROJ + t] = acc;
    __syncthreads();
    if (t < NUM_CLASSES) {
        float la = bc[t];
        for (int k = 0; k < PROJ; k++) la += zs[k] * Wc[k * NUM_CLASSES + t];
        out[N_GRAPHS * PROJ + gph * NUM_CLASSES + t] = la;
    }
}

// ---------------- launch ----------------
extern "C" void kernel_launch(void* const* d_in, const int* in_sizes, int n_in,
                              void* d_out, int out_size) {
    const float* x = (const float*)d_in[0];
    const void* ei = d_in[1];
    const void* batch = d_in[2];
    const float* W1 = (const float*)d_in[3];
    const float* b1 = (const float*)d_in[4];
    const float* bng = (const float*)d_in[5];
    const float* bnb = (const float*)d_in[6];
    const float* bnm = (const float*)d_in[7];
    const float* bnv = (const float*)d_in[8];
    const float* W2 = (const float*)d_in[9];
    const float* b2 = (const float*)d_in[10];
    const float* Wp = (const float*)d_in[11];
    const float* bp = (const float*)d_in[12];
    const float* Wc = (const float*)d_in[13];
    const float* bc = (const float*)d_in[14];
    float* out = (float*)d_out;

    cudaFuncSetAttribute(mlp_kernel, cudaFuncAttributeMaxDynamicSharedMemorySize, SMEM_MLP);

    detect_kernel<<<1, 1>>>((const int*)ei);
    zero_kernel<<<400, 256>>>();
    hist_edges<<<(N_EDGES + 255) / 256, 256>>>(ei);
    hist_batch<<<98, 1024>>>(batch);
    scan1<<<98, 1024>>>();
    scan2<<<1, 1>>>();
    scan3<<<(N_NODES + 255) / 256, 256>>>();
    scatter_edges<<<(N_EDGES + 255) / 256, 256>>>(ei);
    convert_weights<<<(L * 4 * 2048 + 255) / 256, 256>>>(W1, W2, b1, bng, bnb, bnm, bnv);

    for (int l = 0; l < L; l++) {
        mlp_kernel<<<(N_NODES + 127) / 128, 256, SMEM_MLP>>>(l, x, b2);
        pool_kernel<<<(N_NODES + POOL_NODES - 1) / POOL_NODES, 128>>>(batch, l);
    }
    head_kernel<<<N_GRAPHS, PROJ>>>(Wp, bp, Wc, bc, out);
}

// round 9
// speedup vs baseline: 1.2471x; 1.2471x over previous
#include <cuda_runtime.h>
#include <cuda_bf16.h>
#include <cstdint>

#define N_NODES 100000
#define N_EDGES 1600000
#define N_GRAPHS 256
#define D 128
#define L 3
#define PROJ 128
#define NUM_CLASSES 10

// ---------------- device scratch ----------------
__device__ float g_h[N_NODES * D];
__device__ float g_agg[N_NODES * D];
__device__ int   g_counts[N_NODES];
__device__ int   g_offs[N_NODES];
__device__ int   g_cursor[N_NODES];
__device__ int   g_bsum[128];
__device__ int   g_eidx[N_EDGES];
__device__ int   g_cg[N_GRAPHS];
__device__ float g_pooled[L * N_GRAPHS * D];
// packed mma-fragment weights: [l][mat(4)][2048] uint4; mat: 0=w1hi 1=w1lo 2=w2hi 3=w2lo
__device__ __align__(16) uint4 g_wpack[L * 4 * 2048];
__device__ float g_b1e[L * D];
__device__ int   g_is64;

// ---------------- dtype detection: int64 vs int32 indices ----------------
__global__ void detect_kernel(const int* __restrict__ ei_words) {
    int all0 = 1;
    for (int i = 1; i < 128; i += 2)
        if (ei_words[i] != 0) { all0 = 0; break; }
    g_is64 = all0;
}

__device__ __forceinline__ int idx_at(const void* p, long long i) {
    if (g_is64) return (int)__ldg(&((const long long*)p)[i]);
    return __ldg(&((const int*)p)[i]);
}

// ---------------- setup kernels ----------------
__global__ void zero_kernel() {
    int i = blockIdx.x * blockDim.x + threadIdx.x;
    if (i < N_NODES) g_counts[i] = 0;
    if (i < N_GRAPHS) g_cg[i] = 0;
    if (i < L * N_GRAPHS * D) g_pooled[i] = 0.f;
}

__global__ void hist_edges(const void* __restrict__ ei) {
    int e = blockIdx.x * blockDim.x + threadIdx.x;
    if (e < N_EDGES) {
        int d = idx_at(ei, (long long)N_EDGES + e);
        atomicAdd(&g_counts[d], 1);
    }
}

// smem histogram: batch is sorted so each block touches few graphs
__global__ void hist_batch(const void* __restrict__ batch) {
    __shared__ int sh[N_GRAPHS];
    int tid = threadIdx.x;
    if (tid < N_GRAPHS) sh[tid] = 0;
    __syncthreads();
    int i = blockIdx.x * 1024 + tid;
    if (i < N_NODES) atomicAdd(&sh[idx_at(batch, i)], 1);
    __syncthreads();
    if (tid < N_GRAPHS && sh[tid]) atomicAdd(&g_cg[tid], sh[tid]);
}

__global__ void scan1() {
    __shared__ int s[1024];
    int i = blockIdx.x * 1024 + threadIdx.x;
    int v = (i < N_NODES) ? g_counts[i] : 0;
    s[threadIdx.x] = v;
    __syncthreads();
    for (int d = 1; d < 1024; d <<= 1) {
        int t = 0;
        if ((int)threadIdx.x >= d) t = s[threadIdx.x - d];
        __syncthreads();
        s[threadIdx.x] += t;
        __syncthreads();
    }
    if (i < N_NODES) g_offs[i] = s[threadIdx.x] - v;  // exclusive
    if (threadIdx.x == 1023) g_bsum[blockIdx.x] = s[1023];
}

__global__ void scan2() {
    int acc = 0;
    for (int b = 0; b < 98; b++) { int v = g_bsum[b]; g_bsum[b] = acc; acc += v; }
}

__global__ void scan3() {
    int i = blockIdx.x * blockDim.x + threadIdx.x;
    if (i < N_NODES) {
        int off = g_offs[i] + g_bsum[i >> 10];
        g_offs[i] = off;
        g_cursor[i] = off;
    }
}

__global__ void scatter_edges(const void* __restrict__ ei) {
    int e = blockIdx.x * blockDim.x + threadIdx.x;
    if (e < N_EDGES) {
        int d = idx_at(ei, (long long)N_EDGES + e);
        int s = idx_at(ei, e);
        int p = atomicAdd(&g_cursor[d], 1);
        g_eidx[p] = s;
    }
}

// ---------------- weight conversion: fold BN, split hi/lo, pack to fragment order ----------------
// Fragment layout per matrix (2048 uint4): index = (kk*8 + nbp)*32 + lane.
// uint4 = { (n0,kb),(n0,kb+1) | (n0,kb+8),(n0,kb+9) | (n1,kb..) | (n1,kb+8..) }
// with g=lane>>2, t4=lane&3, kb=kk*16+t4*2, n0=(2*nbp)*8+g, n1=n0+8.
__device__ __forceinline__ uint32_t pack2(float a, float b, int lo) {
    __nv_bfloat16 ha = __float2bfloat16(a), hb = __float2bfloat16(b);
    if (lo) {
        ha = __float2bfloat16(a - __bfloat162float(__float2bfloat16(a)));
        hb = __float2bfloat16(b - __bfloat162float(__float2bfloat16(b)));
    }
    return (uint32_t)(*(unsigned short*)&ha) | ((uint32_t)(*(unsigned short*)&hb) << 16);
}

__global__ void convert_weights(const float* __restrict__ W1, const float* __restrict__ W2,
                                const float* __restrict__ b1,
                                const float* __restrict__ bng, const float* __restrict__ bnb,
                                const float* __restrict__ bnm, const float* __restrict__ bnv) {
    int t = blockIdx.x * blockDim.x + threadIdx.x;
    if (t < L * D) {
        float scale = bng[t] * rsqrtf(bnv[t] + 1e-5f);
        g_b1e[t] = (b1[t] - bnm[t]) * scale + bnb[t];
    }
    if (t >= L * 4 * 2048) return;
    int l = t / (4 * 2048);
    int r = t % (4 * 2048);
    int mat = r / 2048;          // 0=w1hi 1=w1lo 2=w2hi 3=w2lo
    int fg = (r % 2048) / 32;    // kk*8+nbp
    int lane = r % 32;
    int kk = fg >> 3, nbp = fg & 7;
    int g = lane >> 2, t4 = lane & 3;
    int kb = kk * 16 + t4 * 2;
    int n0 = (2 * nbp) * 8 + g;
    int n1 = n0 + 8;
    const float* W = (mat < 2) ? W1 : W2;
    int lo = mat & 1;
    // W[l][k][n]; fold BN scale into W1 (per output column n)
    float s0 = 1.f, s1 = 1.f;
    if (mat < 2) {
        s0 = bng[l * D + n0] * rsqrtf(bnv[l * D + n0] + 1e-5f);
        s1 = bng[l * D + n1] * rsqrtf(bnv[l * D + n1] + 1e-5f);
    }
    const float* Wl = W + l * D * D;
    uint4 v;
    v.x = pack2(Wl[kb * D + n0] * s0, Wl[(kb + 1) * D + n0] * s0, lo);
    v.y = pack2(Wl[(kb + 8) * D + n0] * s0, Wl[(kb + 9) * D + n0] * s0, lo);
    v.z = pack2(Wl[kb * D + n1] * s1, Wl[(kb + 1) * D + n1] * s1, lo);
    v.w = pack2(Wl[(kb + 8) * D + n1] * s1, Wl[(kb + 9) * D + n1] * s1, lo);
    g_wpack[t] = v;
}

// ---------------- aggregation: agg[i] = h[i] + sum_{j->i} h[j] ----------------
// high-occupancy: 0 smem, 1 warp per node, near-full SM residency
__global__ void aggregate_kernel(const float* __restrict__ x, int l) {
    int wid = threadIdx.x >> 5, lane = threadIdx.x & 31;
    int node = blockIdx.x * 8 + wid;
    if (node >= N_NODES) return;
    const float4* h4 = (const float4*)((l == 0) ? x : (const float*)g_h);
    float4 acc = h4[node * 32 + lane];
    int s = g_offs[node];
    int e = s + g_counts[node];
    for (int i = s; i < e; i++) {
        int src = g_eidx[i];
        float4 v = __ldg(&h4[src * 32 + lane]);
        acc.x += v.x; acc.y += v.y; acc.z += v.z; acc.w += v.w;
    }
    ((float4*)g_agg)[node * 32 + lane] = acc;
}

// ---------------- MLP (Linear+BN+ReLU+Linear+ReLU) via packed-fragment bf16 mma ----------------
__device__ __forceinline__ void mma_bf16(float* c,
                                         uint32_t a0, uint32_t a1, uint32_t a2, uint32_t a3,
                                         uint32_t b0, uint32_t b1) {
    asm volatile(
        "mma.sync.aligned.m16n8k16.row.col.f32.bf16.bf16.f32 "
        "{%0,%1,%2,%3}, {%4,%5,%6,%7}, {%8,%9}, {%0,%1,%2,%3};"
        : "+f"(c[0]), "+f"(c[1]), "+f"(c[2]), "+f"(c[3])
        : "r"(a0), "r"(a1), "r"(a2), "r"(a3), "r"(b0), "r"(b1));
}

#define SM_PITCH 136

__device__ __forceinline__ void gemm_pass(const __nv_bfloat16* sA, const uint4* __restrict__ wp,
                                          int r0, int lane, int t4, float acc[16][4]) {
#pragma unroll
    for (int kk = 0; kk < 8; kk++) {
        int kb = kk * 16 + t4 * 2;
        uint32_t a0 = *(const uint32_t*)(sA + r0 * SM_PITCH + kb);
        uint32_t a1 = *(const uint32_t*)(sA + (r0 + 8) * SM_PITCH + kb);
        uint32_t a2 = *(const uint32_t*)(sA + r0 * SM_PITCH + kb + 8);
        uint32_t a3 = *(const uint32_t*)(sA + (r0 + 8) * SM_PITCH + kb + 8);
        const uint4* base = wp + kk * 8 * 32 + lane;
#pragma unroll
        for (int nbp = 0; nbp < 8; nbp++) {
            uint4 b = __ldg(base + nbp * 32);
            mma_bf16(acc[2 * nbp], a0, a1, a2, a3, b.x, b.y);
            mma_bf16(acc[2 * nbp + 1], a0, a1, a2, a3, b.z, b.w);
        }
    }
}

__device__ __forceinline__ void store_split(__nv_bfloat16* sHi, __nv_bfloat16* sLo,
                                            int r, int c, float x, float y) {
    __nv_bfloat16 hx = __float2bfloat16(x), hy = __float2bfloat16(y);
    unsigned int uh = (unsigned)(*(unsigned short*)&hx) | ((unsigned)(*(unsigned short*)&hy) << 16);
    __nv_bfloat16 lx = __float2bfloat16(x - __bfloat162float(hx));
    __nv_bfloat16 ly = __float2bfloat16(y - __bfloat162float(hy));
    unsigned int ul = (unsigned)(*(unsigned short*)&lx) | ((unsigned)(*(unsigned short*)&ly) << 16);
    *(unsigned int*)(sHi + r * SM_PITCH + c) = uh;
    *(unsigned int*)(sLo + r * SM_PITCH + c) = ul;
}

#define SMEM_MLP (2 * 128 * SM_PITCH * 2)

__global__ void __launch_bounds__(256) mlp_kernel(int l, const float* __restrict__ b2all) {
    extern __shared__ __nv_bfloat16 sm[];
    __nv_bfloat16* sHi = sm;
    __nv_bfloat16* sLo = sm + 128 * SM_PITCH;
    const int tid = threadIdx.x;
    const int tile = blockIdx.x * 128;

    // load agg tile (coalesced), split to hi/lo bf16
    for (int i = tid; i < 128 * 128 / 2; i += 256) {
        int r = i >> 6;           // 0..127
        int c = (i & 63) * 2;     // even columns
        int row = tile + r;
        float2 v = (row < N_NODES) ? *(const float2*)&g_agg[row * 128 + c]
                                   : make_float2(0.f, 0.f);
        store_split(sHi, sLo, r, c, v.x, v.y);
    }
    __syncthreads();

    const int wid = tid >> 5, lane = tid & 31;
    const int g = lane >> 2, t4 = lane & 3;
    const int r0 = wid * 16 + g;

    const uint4* wl = g_wpack + l * 4 * 2048;
    const float* b1e = g_b1e + l * D;
    const float* b2 = b2all + l * D;

    float acc[16][4];
#pragma unroll
    for (int nb = 0; nb < 16; nb++)
#pragma unroll
        for (int j = 0; j < 4; j++) acc[nb][j] = 0.f;

    // GEMM1: 3-term compensated bf16 (BN folded into w1/b1e)
    gemm_pass(sHi, wl + 0 * 2048, r0, lane, t4, acc);  // hi*hi
    gemm_pass(sHi, wl + 1 * 2048, r0, lane, t4, acc);  // hi*lo
    gemm_pass(sLo, wl + 0 * 2048, r0, lane, t4, acc);  // lo*hi
    __syncthreads();

    // epilogue1: +b1e, relu, resplit to smem
#pragma unroll
    for (int nb = 0; nb < 16; nb++) {
        int c0 = nb * 8 + t4 * 2;
        float bb0 = b1e[c0], bb1 = b1e[c0 + 1];
        float v00 = fmaxf(acc[nb][0] + bb0, 0.f);
        float v01 = fmaxf(acc[nb][1] + bb1, 0.f);
        float v10 = fmaxf(acc[nb][2] + bb0, 0.f);
        float v11 = fmaxf(acc[nb][3] + bb1, 0.f);
        store_split(sHi, sLo, r0, c0, v00, v01);
        store_split(sHi, sLo, r0 + 8, c0, v10, v11);
    }
    __syncthreads();

#pragma unroll
    for (int nb = 0; nb < 16; nb++)
#pragma unroll
        for (int j = 0; j < 4; j++) acc[nb][j] = 0.f;

    // GEMM2
    gemm_pass(sHi, wl + 2 * 2048, r0, lane, t4, acc);
    gemm_pass(sHi, wl + 3 * 2048, r0, lane, t4, acc);
    gemm_pass(sLo, wl + 2 * 2048, r0, lane, t4, acc);

    // epilogue2: +b2, relu, store h
    int row0 = tile + r0;
    int row1 = tile + r0 + 8;
#pragma unroll
    for (int nb = 0; nb < 16; nb++) {
        int c0 = nb * 8 + t4 * 2;
        float bb0 = b2[c0], bb1 = b2[c0 + 1];
        float v00 = fmaxf(acc[nb][0] + bb0, 0.f);
        float v01 = fmaxf(acc[nb][1] + bb1, 0.f);
        float v10 = fmaxf(acc[nb][2] + bb0, 0.f);
        float v11 = fmaxf(acc[nb][3] + bb1, 0.f);
        if (row0 < N_NODES) *(float2*)&g_h[row0 * 128 + c0] = make_float2(v00, v01);
        if (row1 < N_NODES) *(float2*)&g_h[row1 * 128 + c0] = make_float2(v10, v11);
    }
}

// ---------------- pooling: segment-sum of h into pooled[l] ----------------
#define POOL_NODES 512
__global__ void pool_kernel(const void* __restrict__ batch, int l) {
    int t = threadIdx.x;  // 0..127 feature index
    int start = blockIdx.x * POOL_NODES;
    if (start >= N_NODES) return;
    int end = min(start + POOL_NODES, N_NODES);
    int cur = idx_at(batch, start);
    float acc = 0.f;
    for (int n = start; n < end; n++) {
        int gid = idx_at(batch, n);
        if (gid != cur) {
            atomicAdd(&g_pooled[(l * N_GRAPHS + cur) * D + t], acc);
            acc = 0.f;
            cur = gid;
        }
        acc += g_h[n * D + t];
    }
    atomicAdd(&g_pooled[(l * N_GRAPHS + cur) * D + t], acc);
}

// ---------------- head ----------------
__global__ void head_kernel(const float* __restrict__ Wp, const float* __restrict__ bp,
                            const float* __restrict__ Wc, const float* __restrict__ bc,
                            float* __restrict__ out) {
    __shared__ float zs[PROJ];
    int gph = blockIdx.x, t = threadIdx.x;
    float inv = 1.f / fmaxf((float)g_cg[gph], 1.f);
    float acc = bp[t];
#pragma unroll
    for (int l = 0; l < L; l++) {
        const float* pl = &g_pooled[(l * N_GRAPHS + gph) * D];
#pragma unroll 4
        for (int k = 0; k < D; k++) acc += pl[k] * inv * Wp[(l * D + k) * PROJ + t];
    }
    zs[t] = acc;
    out[gph * PROJ + t] = acc;
    __syncthreads();
    if (t < NUM_CLASSES) {
        float la = bc[t];
        for (int k = 0; k < PROJ; k++) la += zs[k] * Wc[k * NUM_CLASSES + t];
        out[N_GRAPHS * PROJ + gph * NUM_CLASSES + t] = la;
    }
}

// ---------------- launch ----------------
extern "C" void kernel_launch(void* const* d_in, const int* in_sizes, int n_in,
                              void* d_out, int out_size) {
    const float* x = (const float*)d_in[0];
    const void* ei = d_in[1];
    const void* batch = d_in[2];
    const float* W1 = (const float*)d_in[3];
    const float* b1 = (const float*)d_in[4];
    const float* bng = (const float*)d_in[5];
    const float* bnb = (const float*)d_in[6];
    const float* bnm = (const float*)d_in[7];
    const float* bnv = (const float*)d_in[8];
    const float* W2 = (const float*)d_in[9];
    const float* b2 = (const float*)d_in[10];
    const float* Wp = (const float*)d_in[11];
    const float* bp = (const float*)d_in[12];
    const float* Wc = (const float*)d_in[13];
    const float* bc = (const float*)d_in[14];
    float* out = (float*)d_out;

    cudaFuncSetAttribute(mlp_kernel, cudaFuncAttributeMaxDynamicSharedMemorySize, SMEM_MLP);

    detect_kernel<<<1, 1>>>((const int*)ei);
    zero_kernel<<<400, 256>>>();
    hist_edges<<<(N_EDGES + 255) / 256, 256>>>(ei);
    hist_batch<<<98, 1024>>>(batch);
    scan1<<<98, 1024>>>();
    scan2<<<1, 1>>>();
    scan3<<<(N_NODES + 255) / 256, 256>>>();
    scatter_edges<<<(N_EDGES + 255) / 256, 256>>>(ei);
    convert_weights<<<(L * 4 * 2048 + 255) / 256, 256>>>(W1, W2, b1, bng, bnb, bnm, bnv);

    for (int l = 0; l < L; l++) {
        aggregate_kernel<<<12500, 256>>>(x, l);
        mlp_kernel<<<(N_NODES + 127) / 128, 256, SMEM_MLP>>>(l, b2);
        pool_kernel<<<(N_NODES + POOL_NODES - 1) / POOL_NODES, 128>>>(batch, l);
    }
    head_kernel<<<N_GRAPHS, PROJ>>>(Wp, bp, Wc, bc, out);
}

// round 11
// speedup vs baseline: 1.8975x; 1.5215x over previous
#include <cuda_runtime.h>
#include <cuda_bf16.h>
#include <cstdint>

#define N_NODES 100000
#define N_EDGES 1600000
#define N_GRAPHS 256
#define D 128
#define L 3
#define PROJ 128
#define NUM_CLASSES 10

// ---------------- device scratch ----------------
__device__ float g_h[N_NODES * D];
__device__ float g_agg[N_NODES * D];
__device__ int   g_counts[N_NODES];
__device__ int   g_offs[N_NODES];
__device__ int   g_cursor[N_NODES];
__device__ int   g_bsum[128];
__device__ int   g_eidx[N_EDGES];
__device__ int   g_cg[N_GRAPHS];
__device__ float g_pooled[L * N_GRAPHS * D];
// packed mma-fragment weights: [l][mat(4)][2048] uint4; mat: 0=w1hi 1=w1lo 2=w2hi 3=w2lo
__device__ __align__(16) uint4 g_wpack[L * 4 * 2048];
__device__ float g_b1e[L * D];
__device__ int   g_is64;

// ---------------- dtype detection: int64 vs int32 indices ----------------
__global__ void detect_kernel(const int* __restrict__ ei_words) {
    int all0 = 1;
    for (int i = 1; i < 128; i += 2)
        if (ei_words[i] != 0) { all0 = 0; break; }
    g_is64 = all0;
}

__device__ __forceinline__ int idx_at(const void* p, long long i) {
    if (g_is64) return (int)__ldg(&((const long long*)p)[i]);
    return __ldg(&((const int*)p)[i]);
}

// ---------------- setup kernels ----------------
__global__ void zero_kernel() {
    int i = blockIdx.x * blockDim.x + threadIdx.x;
    if (i < N_NODES) g_counts[i] = 0;
    if (i < N_GRAPHS) g_cg[i] = 0;
    if (i < L * N_GRAPHS * D) g_pooled[i] = 0.f;
}

__global__ void hist_edges(const void* __restrict__ ei) {
    int e = blockIdx.x * blockDim.x + threadIdx.x;
    if (e < N_EDGES) {
        int d = idx_at(ei, (long long)N_EDGES + e);
        atomicAdd(&g_counts[d], 1);
    }
}

// smem histogram: batch is sorted so each block touches few graphs
__global__ void hist_batch(const void* __restrict__ batch) {
    __shared__ int sh[N_GRAPHS];
    int tid = threadIdx.x;
    if (tid < N_GRAPHS) sh[tid] = 0;
    __syncthreads();
    int i = blockIdx.x * 1024 + tid;
    if (i < N_NODES) atomicAdd(&sh[idx_at(batch, i)], 1);
    __syncthreads();
    if (tid < N_GRAPHS && sh[tid]) atomicAdd(&g_cg[tid], sh[tid]);
}

__global__ void scan1() {
    __shared__ int s[1024];
    int i = blockIdx.x * 1024 + threadIdx.x;
    int v = (i < N_NODES) ? g_counts[i] : 0;
    s[threadIdx.x] = v;
    __syncthreads();
    for (int d = 1; d < 1024; d <<= 1) {
        int t = 0;
        if ((int)threadIdx.x >= d) t = s[threadIdx.x - d];
        __syncthreads();
        s[threadIdx.x] += t;
        __syncthreads();
    }
    if (i < N_NODES) g_offs[i] = s[threadIdx.x] - v;  // exclusive
    if (threadIdx.x == 1023) g_bsum[blockIdx.x] = s[1023];
}

__global__ void scan2() {
    int acc = 0;
    for (int b = 0; b < 98; b++) { int v = g_bsum[b]; g_bsum[b] = acc; acc += v; }
}

__global__ void scan3() {
    int i = blockIdx.x * blockDim.x + threadIdx.x;
    if (i < N_NODES) {
        int off = g_offs[i] + g_bsum[i >> 10];
        g_offs[i] = off;
        g_cursor[i] = off;
    }
}

__global__ void scatter_edges(const void* __restrict__ ei) {
    int e = blockIdx.x * blockDim.x + threadIdx.x;
    if (e < N_EDGES) {
        int d = idx_at(ei, (long long)N_EDGES + e);
        int s = idx_at(ei, e);
        int p = atomicAdd(&g_cursor[d], 1);
        g_eidx[p] = s;
    }
}

// ---------------- weight conversion: fold BN, split hi/lo, pack to fragment order ----------------
__device__ __forceinline__ uint32_t pack2(float a, float b, int lo) {
    __nv_bfloat16 ha = __float2bfloat16(a), hb = __float2bfloat16(b);
    if (lo) {
        ha = __float2bfloat16(a - __bfloat162float(__float2bfloat16(a)));
        hb = __float2bfloat16(b - __bfloat162float(__float2bfloat16(b)));
    }
    return (uint32_t)(*(unsigned short*)&ha) | ((uint32_t)(*(unsigned short*)&hb) << 16);
}

__global__ void convert_weights(const float* __restrict__ W1, const float* __restrict__ W2,
                                const float* __restrict__ b1,
                                const float* __restrict__ bng, const float* __restrict__ bnb,
                                const float* __restrict__ bnm, const float* __restrict__ bnv) {
    int t = blockIdx.x * blockDim.x + threadIdx.x;
    if (t < L * D) {
        float scale = bng[t] * rsqrtf(bnv[t] + 1e-5f);
        g_b1e[t] = (b1[t] - bnm[t]) * scale + bnb[t];
    }
    if (t >= L * 4 * 2048) return;
    int l = t / (4 * 2048);
    int r = t % (4 * 2048);
    int mat = r / 2048;          // 0=w1hi 1=w1lo 2=w2hi 3=w2lo
    int fg = (r % 2048) / 32;    // kk*8+nbp
    int lane = r % 32;
    int kk = fg >> 3, nbp = fg & 7;
    int g = lane >> 2, t4 = lane & 3;
    int kb = kk * 16 + t4 * 2;
    int n0 = (2 * nbp) * 8 + g;
    int n1 = n0 + 8;
    const float* W = (mat < 2) ? W1 : W2;
    int lo = mat & 1;
    float s0 = 1.f, s1 = 1.f;
    if (mat < 2) {
        s0 = bng[l * D + n0] * rsqrtf(bnv[l * D + n0] + 1e-5f);
        s1 = bng[l * D + n1] * rsqrtf(bnv[l * D + n1] + 1e-5f);
    }
    const float* Wl = W + l * D * D;
    uint4 v;
    v.x = pack2(Wl[kb * D + n0] * s0, Wl[(kb + 1) * D + n0] * s0, lo);
    v.y = pack2(Wl[(kb + 8) * D + n0] * s0, Wl[(kb + 9) * D + n0] * s0, lo);
    v.z = pack2(Wl[kb * D + n1] * s1, Wl[(kb + 1) * D + n1] * s1, lo);
    v.w = pack2(Wl[(kb + 8) * D + n1] * s1, Wl[(kb + 9) * D + n1] * s1, lo);
    g_wpack[t] = v;
}

// ---------------- aggregation: agg[i] = h[i] + sum_{j->i} h[j] ----------------
// high-occupancy, unroll-4 gather: 4 independent edge-row loads in flight per warp
__global__ void aggregate_kernel(const float* __restrict__ x, int l) {
    int wid = threadIdx.x >> 5, lane = threadIdx.x & 31;
    int node = blockIdx.x * 8 + wid;
    if (node >= N_NODES) return;
    const float4* h4 = (const float4*)((l == 0) ? x : (const float*)g_h);
    float4 a0 = h4[node * 32 + lane];
    float4 a1 = make_float4(0.f, 0.f, 0.f, 0.f);
    float4 a2 = make_float4(0.f, 0.f, 0.f, 0.f);
    float4 a3 = make_float4(0.f, 0.f, 0.f, 0.f);
    int s = g_offs[node];
    int e = s + g_counts[node];
    int i = s;
    for (; i + 4 <= e; i += 4) {
        int s0 = __ldg(&g_eidx[i]);
        int s1 = __ldg(&g_eidx[i + 1]);
        int s2 = __ldg(&g_eidx[i + 2]);
        int s3 = __ldg(&g_eidx[i + 3]);
        float4 v0 = __ldg(&h4[s0 * 32 + lane]);
        float4 v1 = __ldg(&h4[s1 * 32 + lane]);
        float4 v2 = __ldg(&h4[s2 * 32 + lane]);
        float4 v3 = __ldg(&h4[s3 * 32 + lane]);
        a0.x += v0.x; a0.y += v0.y; a0.z += v0.z; a0.w += v0.w;
        a1.x += v1.x; a1.y += v1.y; a1.z += v1.z; a1.w += v1.w;
        a2.x += v2.x; a2.y += v2.y; a2.z += v2.z; a2.w += v2.w;
        a3.x += v3.x; a3.y += v3.y; a3.z += v3.z; a3.w += v3.w;
    }
    for (; i < e; i++) {
        int src = __ldg(&g_eidx[i]);
        float4 v = __ldg(&h4[src * 32 + lane]);
        a0.x += v.x; a0.y += v.y; a0.z += v.z; a0.w += v.w;
    }
    a0.x += a1.x + a2.x + a3.x;
    a0.y += a1.y + a2.y + a3.y;
    a0.z += a1.z + a2.z + a3.z;
    a0.w += a1.w + a2.w + a3.w;
    ((float4*)g_agg)[node * 32 + lane] = a0;
}

// ---------------- MLP (Linear+BN+ReLU+Linear+ReLU) via packed-fragment bf16 mma ----------------
__device__ __forceinline__ void mma_bf16(float* c,
                                         uint32_t a0, uint32_t a1, uint32_t a2, uint32_t a3,
                                         uint32_t b0, uint32_t b1) {
    asm volatile(
        "mma.sync.aligned.m16n8k16.row.col.f32.bf16.bf16.f32 "
        "{%0,%1,%2,%3}, {%4,%5,%6,%7}, {%8,%9}, {%0,%1,%2,%3};"
        : "+f"(c[0]), "+f"(c[1]), "+f"(c[2]), "+f"(c[3])
        : "r"(a0), "r"(a1), "r"(a2), "r"(a3), "r"(b0), "r"(b1));
}

#define SM_PITCH 136

__device__ __forceinline__ void gemm_pass(const __nv_bfloat16* sA, const uint4* __restrict__ wp,
                                          int r0, int lane, int t4, float acc[16][4]) {
#pragma unroll
    for (int kk = 0; kk < 8; kk++) {
        int kb = kk * 16 + t4 * 2;
        uint32_t a0 = *(const uint32_t*)(sA + r0 * SM_PITCH + kb);
        uint32_t a1 = *(const uint32_t*)(sA + (r0 + 8) * SM_PITCH + kb);
        uint32_t a2 = *(const uint32_t*)(sA + r0 * SM_PITCH + kb + 8);
        uint32_t a3 = *(const uint32_t*)(sA + (r0 + 8) * SM_PITCH + kb + 8);
        const uint4* base = wp + kk * 8 * 32 + lane;
#pragma unroll
        for (int nbp = 0; nbp < 8; nbp++) {
            uint4 b = __ldg(base + nbp * 32);
            mma_bf16(acc[2 * nbp], a0, a1, a2, a3, b.x, b.y);
            mma_bf16(acc[2 * nbp + 1], a0, a1, a2, a3, b.z, b.w);
        }
    }
}

__device__ __forceinline__ void store_split(__nv_bfloat16* sHi, __nv_bfloat16* sLo,
                                            int r, int c, float x, float y) {
    __nv_bfloat16 hx = __float2bfloat16(x), hy = __float2bfloat16(y);
    unsigned int uh = (unsigned)(*(unsigned short*)&hx) | ((unsigned)(*(unsigned short*)&hy) << 16);
    __nv_bfloat16 lx = __float2bfloat16(x - __bfloat162float(hx));
    __nv_bfloat16 ly = __float2bfloat16(y - __bfloat162float(hy));
    unsigned int ul = (unsigned)(*(unsigned short*)&lx) | ((unsigned)(*(unsigned short*)&ly) << 16);
    *(unsigned int*)(sHi + r * SM_PITCH + c) = uh;
    *(unsigned int*)(sLo + r * SM_PITCH + c) = ul;
}

#define SMEM_MLP (2 * 128 * SM_PITCH * 2)

__global__ void __launch_bounds__(256) mlp_kernel(int l, const float* __restrict__ b2all) {
    extern __shared__ __nv_bfloat16 sm[];
    __nv_bfloat16* sHi = sm;
    __nv_bfloat16* sLo = sm + 128 * SM_PITCH;
    const int tid = threadIdx.x;
    const int tile = blockIdx.x * 128;

    // load agg tile (coalesced), split to hi/lo bf16
    for (int i = tid; i < 128 * 128 / 2; i += 256) {
        int r = i >> 6;           // 0..127
        int c = (i & 63) * 2;     // even columns
        int row = tile + r;
        float2 v = (row < N_NODES) ? *(const float2*)&g_agg[row * 128 + c]
                                   : make_float2(0.f, 0.f);
        store_split(sHi, sLo, r, c, v.x, v.y);
    }
    __syncthreads();

    const int wid = tid >> 5, lane = tid & 31;
    const int g = lane >> 2, t4 = lane & 3;
    const int r0 = wid * 16 + g;

    const uint4* wl = g_wpack + l * 4 * 2048;
    const float* b1e = g_b1e + l * D;
    const float* b2 = b2all + l * D;

    float acc[16][4];
#pragma unroll
    for (int nb = 0; nb < 16; nb++)
#pragma unroll
        for (int j = 0; j < 4; j++) acc[nb][j] = 0.f;

    // GEMM1: 3-term compensated bf16 (BN folded into w1/b1e)
    gemm_pass(sHi, wl + 0 * 2048, r0, lane, t4, acc);  // hi*hi
    gemm_pass(sHi, wl + 1 * 2048, r0, lane, t4, acc);  // hi*lo
    gemm_pass(sLo, wl + 0 * 2048, r0, lane, t4, acc);  // lo*hi
    __syncthreads();

    // epilogue1: +b1e, relu, resplit to smem
#pragma unroll
    for (int nb = 0; nb < 16; nb++) {
        int c0 = nb * 8 + t4 * 2;
        float bb0 = b1e[c0], bb1 = b1e[c0 + 1];
        float v00 = fmaxf(acc[nb][0] + bb0, 0.f);
        float v01 = fmaxf(acc[nb][1] + bb1, 0.f);
        float v10 = fmaxf(acc[nb][2] + bb0, 0.f);
        float v11 = fmaxf(acc[nb][3] + bb1, 0.f);
        store_split(sHi, sLo, r0, c0, v00, v01);
        store_split(sHi, sLo, r0 + 8, c0, v10, v11);
    }
    __syncthreads();

#pragma unroll
    for (int nb = 0; nb < 16; nb++)
#pragma unroll
        for (int j = 0; j < 4; j++) acc[nb][j] = 0.f;

    // GEMM2
    gemm_pass(sHi, wl + 2 * 2048, r0, lane, t4, acc);
    gemm_pass(sHi, wl + 3 * 2048, r0, lane, t4, acc);
    gemm_pass(sLo, wl + 2 * 2048, r0, lane, t4, acc);

    // epilogue2: +b2, relu, store h
    int row0 = tile + r0;
    int row1 = tile + r0 + 8;
#pragma unroll
    for (int nb = 0; nb < 16; nb++) {
        int c0 = nb * 8 + t4 * 2;
        float bb0 = b2[c0], bb1 = b2[c0 + 1];
        float v00 = fmaxf(acc[nb][0] + bb0, 0.f);
        float v01 = fmaxf(acc[nb][1] + bb1, 0.f);
        float v10 = fmaxf(acc[nb][2] + bb0, 0.f);
        float v11 = fmaxf(acc[nb][3] + bb1, 0.f);
        if (row0 < N_NODES) *(float2*)&g_h[row0 * 128 + c0] = make_float2(v00, v01);
        if (row1 < N_NODES) *(float2*)&g_h[row1 * 128 + c0] = make_float2(v10, v11);
    }
}

// ---------------- pooling: segment-sum of h into pooled[l] ----------------
#define POOL_NODES 128
__global__ void pool_kernel(const void* __restrict__ batch, int l) {
    int t = threadIdx.x;  // 0..127 feature index
    int start = blockIdx.x * POOL_NODES;
    if (start >= N_NODES) return;
    int end = min(start + POOL_NODES, N_NODES);
    int cur = idx_at(batch, start);
    float acc = 0.f;
    for (int n = start; n < end; n++) {
        int gid = idx_at(batch, n);
        if (gid != cur) {
            atomicAdd(&g_pooled[(l * N_GRAPHS + cur) * D + t], acc);
            acc = 0.f;
            cur = gid;
        }
        acc += g_h[n * D + t];
    }
    atomicAdd(&g_pooled[(l * N_GRAPHS + cur) * D + t], acc);
}

// ---------------- head ----------------
__global__ void head_kernel(const float* __restrict__ Wp, const float* __restrict__ bp,
                            const float* __restrict__ Wc, const float* __restrict__ bc,
                            float* __restrict__ out) {
    __shared__ float zs[PROJ];
    int gph = blockIdx.x, t = threadIdx.x;
    float inv = 1.f / fmaxf((float)g_cg[gph], 1.f);
    float acc = bp[t];
#pragma unroll
    for (int l = 0; l < L; l++) {
        const float* pl = &g_pooled[(l * N_GRAPHS + gph) * D];
#pragma unroll 4
        for (int k = 0; k < D; k++) acc += pl[k] * inv * Wp[(l * D + k) * PROJ + t];
    }
    zs[t] = acc;
    out[gph * PROJ + t] = acc;
    __syncthreads();
    if (t < NUM_CLASSES) {
        float la = bc[t];
        for (int k = 0; k < PROJ; k++) la += zs[k] * Wc[k * NUM_CLASSES + t];
        out[N_GRAPHS * PROJ + gph * NUM_CLASSES + t] = la;
    }
}

// ---------------- launch ----------------
extern "C" void kernel_launch(void* const* d_in, const int* in_sizes, int n_in,
                              void* d_out, int out_size) {
    const float* x = (const float*)d_in[0];
    const void* ei = d_in[1];
    const void* batch = d_in[2];
    const float* W1 = (const float*)d_in[3];
    const float* b1 = (const float*)d_in[4];
    const float* bng = (const float*)d_in[5];
    const float* bnb = (const float*)d_in[6];
    const float* bnm = (const float*)d_in[7];
    const float* bnv = (const float*)d_in[8];
    const float* W2 = (const float*)d_in[9];
    const float* b2 = (const float*)d_in[10];
    const float* Wp = (const float*)d_in[11];
    const float* bp = (const float*)d_in[12];
    const float* Wc = (const float*)d_in[13];
    const float* bc = (const float*)d_in[14];
    float* out = (float*)d_out;

    cudaFuncSetAttribute(mlp_kernel, cudaFuncAttributeMaxDynamicSharedMemorySize, SMEM_MLP);

    detect_kernel<<<1, 1>>>((const int*)ei);
    zero_kernel<<<400, 256>>>();
    hist_edges<<<(N_EDGES + 255) / 256, 256>>>(ei);
    hist_batch<<<98, 1024>>>(batch);
    scan1<<<98, 1024>>>();
    scan2<<<1, 1>>>();
    scan3<<<(N_NODES + 255) / 256, 256>>>();
    scatter_edges<<<(N_EDGES + 255) / 256, 256>>>(ei);
    convert_weights<<<(L * 4 * 2048 + 255) / 256, 256>>>(W1, W2, b1, bng, bnb, bnm, bnv);

    for (int l = 0; l < L; l++) {
        aggregate_kernel<<<12500, 256>>>(x, l);
        mlp_kernel<<<(N_NODES + 127) / 128, 256, SMEM_MLP>>>(l, b2);
        pool_kernel<<<(N_NODES + POOL_NODES - 1) / POOL_NODES, 128>>>(batch, l);
    }
    head_kernel<<<N_GRAPHS, PROJ>>>(Wp, bp, Wc, bc, out);
}

// round 12
// speedup vs baseline: 2.2711x; 1.1969x over previous
#include <cuda_runtime.h>
#include <cuda_fp16.h>
#include <cstdint>

#define N_NODES 100000
#define N_EDGES 1600000
#define N_GRAPHS 256
#define D 128
#define L 3
#define PROJ 128
#define NUM_CLASSES 10

// ---------------- device scratch ----------------
__device__ float g_h[N_NODES * D];
__device__ float g_agg[N_NODES * D];
__device__ int   g_counts[N_NODES];
__device__ int   g_offs[N_NODES];
__device__ int   g_cursor[N_NODES];
__device__ int   g_bsum[128];
__device__ int   g_eidx[N_EDGES];
__device__ int   g_cg[N_GRAPHS];
__device__ float g_pooled[L * N_GRAPHS * D];
// packed mma-fragment fp16 weights: [l][mat(2)][2048] uint4; mat: 0=w1(BN-folded) 1=w2
__device__ __align__(16) uint4 g_wpack[L * 2 * 2048];
__device__ float g_b1e[L * D];
__device__ int   g_is64;

// ---------------- dtype detection: int64 vs int32 indices ----------------
__global__ void detect_kernel(const int* __restrict__ ei_words) {
    int all0 = 1;
    for (int i = 1; i < 128; i += 2)
        if (ei_words[i] != 0) { all0 = 0; break; }
    g_is64 = all0;
}

__device__ __forceinline__ int idx_at(const void* p, long long i) {
    if (g_is64) return (int)__ldg(&((const long long*)p)[i]);
    return __ldg(&((const int*)p)[i]);
}

// ---------------- setup kernels ----------------
__global__ void zero_kernel() {
    int i = blockIdx.x * blockDim.x + threadIdx.x;
    if (i < N_NODES) g_counts[i] = 0;
    if (i < N_GRAPHS) g_cg[i] = 0;
    if (i < L * N_GRAPHS * D) g_pooled[i] = 0.f;
}

__global__ void hist_edges(const void* __restrict__ ei) {
    int e = blockIdx.x * blockDim.x + threadIdx.x;
    if (e < N_EDGES) {
        int d = idx_at(ei, (long long)N_EDGES + e);
        atomicAdd(&g_counts[d], 1);
    }
}

// smem histogram: batch is sorted so each block touches few graphs
__global__ void hist_batch(const void* __restrict__ batch) {
    __shared__ int sh[N_GRAPHS];
    int tid = threadIdx.x;
    if (tid < N_GRAPHS) sh[tid] = 0;
    __syncthreads();
    int i = blockIdx.x * 1024 + tid;
    if (i < N_NODES) atomicAdd(&sh[idx_at(batch, i)], 1);
    __syncthreads();
    if (tid < N_GRAPHS && sh[tid]) atomicAdd(&g_cg[tid], sh[tid]);
}

__global__ void scan1() {
    __shared__ int s[1024];
    int i = blockIdx.x * 1024 + threadIdx.x;
    int v = (i < N_NODES) ? g_counts[i] : 0;
    s[threadIdx.x] = v;
    __syncthreads();
    for (int d = 1; d < 1024; d <<= 1) {
        int t = 0;
        if ((int)threadIdx.x >= d) t = s[threadIdx.x - d];
        __syncthreads();
        s[threadIdx.x] += t;
        __syncthreads();
    }
    if (i < N_NODES) g_offs[i] = s[threadIdx.x] - v;  // exclusive
    if (threadIdx.x == 1023) g_bsum[blockIdx.x] = s[1023];
}

__global__ void scan2() {
    int acc = 0;
    for (int b = 0; b < 98; b++) { int v = g_bsum[b]; g_bsum[b] = acc; acc += v; }
}

__global__ void scan3() {
    int i = blockIdx.x * blockDim.x + threadIdx.x;
    if (i < N_NODES) {
        int off = g_offs[i] + g_bsum[i >> 10];
        g_offs[i] = off;
        g_cursor[i] = off;
    }
}

__global__ void scatter_edges(const void* __restrict__ ei) {
    int e = blockIdx.x * blockDim.x + threadIdx.x;
    if (e < N_EDGES) {
        int d = idx_at(ei, (long long)N_EDGES + e);
        int s = idx_at(ei, e);
        int p = atomicAdd(&g_cursor[d], 1);
        g_eidx[p] = s;
    }
}

// ---------------- weight conversion: fold BN, fp16, pack to fragment order ----------------
// Fragment layout per matrix (2048 uint4): index = (kk*8 + nbp)*32 + lane.
// uint4 = { (n0,kb),(n0,kb+1) | (n0,kb+8),(n0,kb+9) | (n1,kb..) | (n1,kb+8..) }
// with g=lane>>2, t4=lane&3, kb=kk*16+t4*2, n0=(2*nbp)*8+g, n1=n0+8.
__device__ __forceinline__ uint32_t pack2h(float a, float b) {
    __half ha = __float2half(a), hb = __float2half(b);
    return (uint32_t)(*(unsigned short*)&ha) | ((uint32_t)(*(unsigned short*)&hb) << 16);
}

__global__ void convert_weights(const float* __restrict__ W1, const float* __restrict__ W2,
                                const float* __restrict__ b1,
                                const float* __restrict__ bng, const float* __restrict__ bnb,
                                const float* __restrict__ bnm, const float* __restrict__ bnv) {
    int t = blockIdx.x * blockDim.x + threadIdx.x;
    if (t < L * D) {
        float scale = bng[t] * rsqrtf(bnv[t] + 1e-5f);
        g_b1e[t] = (b1[t] - bnm[t]) * scale + bnb[t];
    }
    if (t >= L * 2 * 2048) return;
    int l = t / (2 * 2048);
    int r = t % (2 * 2048);
    int mat = r / 2048;          // 0=w1 (BN-folded) 1=w2
    int fg = (r % 2048) / 32;    // kk*8+nbp
    int lane = r % 32;
    int kk = fg >> 3, nbp = fg & 7;
    int g = lane >> 2, t4 = lane & 3;
    int kb = kk * 16 + t4 * 2;
    int n0 = (2 * nbp) * 8 + g;
    int n1 = n0 + 8;
    const float* W = (mat == 0) ? W1 : W2;
    float s0 = 1.f, s1 = 1.f;
    if (mat == 0) {
        s0 = bng[l * D + n0] * rsqrtf(bnv[l * D + n0] + 1e-5f);
        s1 = bng[l * D + n1] * rsqrtf(bnv[l * D + n1] + 1e-5f);
    }
    const float* Wl = W + l * D * D;
    uint4 v;
    v.x = pack2h(Wl[kb * D + n0] * s0, Wl[(kb + 1) * D + n0] * s0);
    v.y = pack2h(Wl[(kb + 8) * D + n0] * s0, Wl[(kb + 9) * D + n0] * s0);
    v.z = pack2h(Wl[kb * D + n1] * s1, Wl[(kb + 1) * D + n1] * s1);
    v.w = pack2h(Wl[(kb + 8) * D + n1] * s1, Wl[(kb + 9) * D + n1] * s1);
    g_wpack[t] = v;
}

// ---------------- aggregation: agg[i] = h[i] + sum_{j->i} h[j] ----------------
// high-occupancy, unroll-4 gather: 4 independent edge-row loads in flight per warp
__global__ void aggregate_kernel(const float* __restrict__ x, int l) {
    int wid = threadIdx.x >> 5, lane = threadIdx.x & 31;
    int node = blockIdx.x * 8 + wid;
    if (node >= N_NODES) return;
    const float4* h4 = (const float4*)((l == 0) ? x : (const float*)g_h);
    float4 a0 = h4[node * 32 + lane];
    float4 a1 = make_float4(0.f, 0.f, 0.f, 0.f);
    float4 a2 = make_float4(0.f, 0.f, 0.f, 0.f);
    float4 a3 = make_float4(0.f, 0.f, 0.f, 0.f);
    int s = g_offs[node];
    int e = s + g_counts[node];
    int i = s;
    for (; i + 4 <= e; i += 4) {
        int s0 = __ldg(&g_eidx[i]);
        int s1 = __ldg(&g_eidx[i + 1]);
        int s2 = __ldg(&g_eidx[i + 2]);
        int s3 = __ldg(&g_eidx[i + 3]);
        float4 v0 = __ldg(&h4[s0 * 32 + lane]);
        float4 v1 = __ldg(&h4[s1 * 32 + lane]);
        float4 v2 = __ldg(&h4[s2 * 32 + lane]);
        float4 v3 = __ldg(&h4[s3 * 32 + lane]);
        a0.x += v0.x; a0.y += v0.y; a0.z += v0.z; a0.w += v0.w;
        a1.x += v1.x; a1.y += v1.y; a1.z += v1.z; a1.w += v1.w;
        a2.x += v2.x; a2.y += v2.y; a2.z += v2.z; a2.w += v2.w;
        a3.x += v3.x; a3.y += v3.y; a3.z += v3.z; a3.w += v3.w;
    }
    for (; i < e; i++) {
        int src = __ldg(&g_eidx[i]);
        float4 v = __ldg(&h4[src * 32 + lane]);
        a0.x += v.x; a0.y += v.y; a0.z += v.z; a0.w += v.w;
    }
    a0.x += a1.x + a2.x + a3.x;
    a0.y += a1.y + a2.y + a3.y;
    a0.z += a1.z + a2.z + a3.z;
    a0.w += a1.w + a2.w + a3.w;
    ((float4*)g_agg)[node * 32 + lane] = a0;
}

// ---------------- MLP via fp16 2-term compensated mma ----------------
__device__ __forceinline__ void mma_f16(float* c,
                                        uint32_t a0, uint32_t a1, uint32_t a2, uint32_t a3,
                                        uint32_t b0, uint32_t b1) {
    asm volatile(
        "mma.sync.aligned.m16n8k16.row.col.f32.f16.f16.f32 "
        "{%0,%1,%2,%3}, {%4,%5,%6,%7}, {%8,%9}, {%0,%1,%2,%3};"
        : "+f"(c[0]), "+f"(c[1]), "+f"(c[2]), "+f"(c[3])
        : "r"(a0), "r"(a1), "r"(a2), "r"(a3), "r"(b0), "r"(b1));
}

#define SM_PITCH 136

__device__ __forceinline__ void gemm_pass(const __half* sA, const uint4* __restrict__ wp,
                                          int r0, int lane, int t4, float acc[16][4]) {
#pragma unroll
    for (int kk = 0; kk < 8; kk++) {
        int kb = kk * 16 + t4 * 2;
        uint32_t a0 = *(const uint32_t*)(sA + r0 * SM_PITCH + kb);
        uint32_t a1 = *(const uint32_t*)(sA + (r0 + 8) * SM_PITCH + kb);
        uint32_t a2 = *(const uint32_t*)(sA + r0 * SM_PITCH + kb + 8);
        uint32_t a3 = *(const uint32_t*)(sA + (r0 + 8) * SM_PITCH + kb + 8);
        const uint4* base = wp + kk * 8 * 32 + lane;
#pragma unroll
        for (int nbp = 0; nbp < 8; nbp++) {
            uint4 b = __ldg(base + nbp * 32);
            mma_f16(acc[2 * nbp], a0, a1, a2, a3, b.x, b.y);
            mma_f16(acc[2 * nbp + 1], a0, a1, a2, a3, b.z, b.w);
        }
    }
}

// split fp32 -> fp16 hi + fp16 lo (hi+lo covers ~22 mantissa bits)
__device__ __forceinline__ void store_split(__half* sHi, __half* sLo,
                                            int r, int c, float x, float y) {
    __half hx = __float2half(x), hy = __float2half(y);
    unsigned int uh = (unsigned)(*(unsigned short*)&hx) | ((unsigned)(*(unsigned short*)&hy) << 16);
    __half lx = __float2half(x - __half2float(hx));
    __half ly = __float2half(y - __half2float(hy));
    unsigned int ul = (unsigned)(*(unsigned short*)&lx) | ((unsigned)(*(unsigned short*)&ly) << 16);
    *(unsigned int*)(sHi + r * SM_PITCH + c) = uh;
    *(unsigned int*)(sLo + r * SM_PITCH + c) = ul;
}

#define SMEM_MLP (2 * 128 * SM_PITCH * 2)

__global__ void __launch_bounds__(256) mlp_kernel(int l, const float* __restrict__ b2all) {
    extern __shared__ __half sm[];
    __half* sHi = sm;
    __half* sLo = sm + 128 * SM_PITCH;
    const int tid = threadIdx.x;
    const int tile = blockIdx.x * 128;

    // load agg tile (coalesced), split to hi/lo fp16
    for (int i = tid; i < 128 * 128 / 2; i += 256) {
        int r = i >> 6;           // 0..127
        int c = (i & 63) * 2;     // even columns
        int row = tile + r;
        float2 v = (row < N_NODES) ? *(const float2*)&g_agg[row * 128 + c]
                                   : make_float2(0.f, 0.f);
        store_split(sHi, sLo, r, c, v.x, v.y);
    }
    __syncthreads();

    const int wid = tid >> 5, lane = tid & 31;
    const int g = lane >> 2, t4 = lane & 3;
    const int r0 = wid * 16 + g;

    const uint4* wl = g_wpack + l * 2 * 2048;
    const float* b1e = g_b1e + l * D;
    const float* b2 = b2all + l * D;

    float acc[16][4];
#pragma unroll
    for (int nb = 0; nb < 16; nb++)
#pragma unroll
        for (int j = 0; j < 4; j++) acc[nb][j] = 0.f;

    // GEMM1: 2-term fp16 (A_hi + A_lo) * W1, BN folded into W1/b1e
    gemm_pass(sHi, wl + 0 * 2048, r0, lane, t4, acc);
    gemm_pass(sLo, wl + 0 * 2048, r0, lane, t4, acc);
    __syncthreads();

    // epilogue1: +b1e, relu, resplit to smem
#pragma unroll
    for (int nb = 0; nb < 16; nb++) {
        int c0 = nb * 8 + t4 * 2;
        float bb0 = b1e[c0], bb1 = b1e[c0 + 1];
        float v00 = fmaxf(acc[nb][0] + bb0, 0.f);
        float v01 = fmaxf(acc[nb][1] + bb1, 0.f);
        float v10 = fmaxf(acc[nb][2] + bb0, 0.f);
        float v11 = fmaxf(acc[nb][3] + bb1, 0.f);
        store_split(sHi, sLo, r0, c0, v00, v01);
        store_split(sHi, sLo, r0 + 8, c0, v10, v11);
    }
    __syncthreads();

#pragma unroll
    for (int nb = 0; nb < 16; nb++)
#pragma unroll
        for (int j = 0; j < 4; j++) acc[nb][j] = 0.f;

    // GEMM2: 2-term fp16
    gemm_pass(sHi, wl + 1 * 2048, r0, lane, t4, acc);
    gemm_pass(sLo, wl + 1 * 2048, r0, lane, t4, acc);

    // epilogue2: +b2, relu, store h
    int row0 = tile + r0;
    int row1 = tile + r0 + 8;
#pragma unroll
    for (int nb = 0; nb < 16; nb++) {
        int c0 = nb * 8 + t4 * 2;
        float bb0 = b2[c0], bb1 = b2[c0 + 1];
        float v00 = fmaxf(acc[nb][0] + bb0, 0.f);
        float v01 = fmaxf(acc[nb][1] + bb1, 0.f);
        float v10 = fmaxf(acc[nb][2] + bb0, 0.f);
        float v11 = fmaxf(acc[nb][3] + bb1, 0.f);
        if (row0 < N_NODES) *(float2*)&g_h[row0 * 128 + c0] = make_float2(v00, v01);
        if (row1 < N_NODES) *(float2*)&g_h[row1 * 128 + c0] = make_float2(v10, v11);
    }
}

// ---------------- pooling: segment-sum of h into pooled[l] ----------------
#define POOL_NODES 128
__global__ void pool_kernel(const void* __restrict__ batch, int l) {
    int t = threadIdx.x;  // 0..127 feature index
    int start = blockIdx.x * POOL_NODES;
    if (start >= N_NODES) return;
    int end = min(start + POOL_NODES, N_NODES);
    int cur = idx_at(batch, start);
    float acc = 0.f;
    for (int n = start; n < end; n++) {
        int gid = idx_at(batch, n);
        if (gid != cur) {
            atomicAdd(&g_pooled[(l * N_GRAPHS + cur) * D + t], acc);
            acc = 0.f;
            cur = gid;
        }
        acc += g_h[n * D + t];
    }
    atomicAdd(&g_pooled[(l * N_GRAPHS + cur) * D + t], acc);
}

// ---------------- head ----------------
__global__ void head_kernel(const float* __restrict__ Wp, const float* __restrict__ bp,
                            const float* __restrict__ Wc, const float* __restrict__ bc,
                            float* __restrict__ out) {
    __shared__ float zs[PROJ];
    int gph = blockIdx.x, t = threadIdx.x;
    float inv = 1.f / fmaxf((float)g_cg[gph], 1.f);
    float acc = bp[t];
#pragma unroll
    for (int l = 0; l < L; l++) {
        const float* pl = &g_pooled[(l * N_GRAPHS + gph) * D];
#pragma unroll 4
        for (int k = 0; k < D; k++) acc += pl[k] * inv * Wp[(l * D + k) * PROJ + t];
    }
    zs[t] = acc;
    out[gph * PROJ + t] = acc;
    __syncthreads();
    if (t < NUM_CLASSES) {
        float la = bc[t];
        for (int k = 0; k < PROJ; k++) la += zs[k] * Wc[k * NUM_CLASSES + t];
        out[N_GRAPHS * PROJ + gph * NUM_CLASSES + t] = la;
    }
}

// ---------------- launch ----------------
extern "C" void kernel_launch(void* const* d_in, const int* in_sizes, int n_in,
                              void* d_out, int out_size) {
    const float* x = (const float*)d_in[0];
    const void* ei = d_in[1];
    const void* batch = d_in[2];
    const float* W1 = (const float*)d_in[3];
    const float* b1 = (const float*)d_in[4];
    const float* bng = (const float*)d_in[5];
    const float* bnb = (const float*)d_in[6];
    const float* bnm = (const float*)d_in[7];
    const float* bnv = (const float*)d_in[8];
    const float* W2 = (const float*)d_in[9];
    const float* b2 = (const float*)d_in[10];
    const float* Wp = (const float*)d_in[11];
    const float* bp = (const float*)d_in[12];
    const float* Wc = (const float*)d_in[13];
    const float* bc = (const float*)d_in[14];
    float* out = (float*)d_out;

    cudaFuncSetAttribute(mlp_kernel, cudaFuncAttributeMaxDynamicSharedMemorySize, SMEM_MLP);

    detect_kernel<<<1, 1>>>((const int*)ei);
    zero_kernel<<<400, 256>>>();
    hist_edges<<<(N_EDGES + 255) / 256, 256>>>(ei);
    hist_batch<<<98, 1024>>>(batch);
    scan1<<<98, 1024>>>();
    scan2<<<1, 1>>>();
    scan3<<<(N_NODES + 255) / 256, 256>>>();
    scatter_edges<<<(N_EDGES + 255) / 256, 256>>>(ei);
    convert_weights<<<(L * 2 * 2048 + 255) / 256, 256>>>(W1, W2, b1, bng, bnb, bnm, bnv);

    for (int l = 0; l < L; l++) {
        aggregate_kernel<<<12500, 256>>>(x, l);
        mlp_kernel<<<(N_NODES + 127) / 128, 256, SMEM_MLP>>>(l, b2);
        pool_kernel<<<(N_NODES + POOL_NODES - 1) / POOL_NODES, 128>>>(batch, l);
    }
    head_kernel<<<N_GRAPHS, PROJ>>>(Wp, bp, Wc, bc, out);
}